// round 1
// baseline (speedup 1.0000x reference)
#include <cuda_runtime.h>
#include <math.h>

#define NN 63
#define NP (NN*NN)          // 3969
#define BATCH 256
#define MID 32
#define KS 7
#define ML 3
#define HALFC 32            // N//2+1

// ---------------- device scratch ----------------
__device__ float g_cosT[NP];
__device__ float g_sinT[NP];
__device__ float g_w1[BATCH*147];
__device__ float g_w2[BATCH*147];
__device__ float g_a1[BATCH*32*5*5];
__device__ float g_a2[BATCH*32*9*9];
__device__ float g_a3[BATCH*32*17*17];
__device__ float g_a4[BATCH*32*33*33];
__device__ float g_h [BATCH*2*NP];
__device__ float g_blocksum[BATCH];

__device__ __forceinline__ float gelu_exact(float v) {
    return v * 0.5f * (1.0f + erff(v * 0.70710678118654752f));
}

// ---------------- twiddle init ----------------
__global__ void init_tw_kernel() {
    int idx = blockIdx.x * blockDim.x + threadIdx.x;
    if (idx < NP) {
        int k = idx / NN, n = idx % NN;
        float ang = 6.28318530717958647692f * (float)((k * n) % NN) / 63.0f;
        g_cosT[idx] = cosf(ang);
        g_sinT[idx] = sinf(ang);
    }
}

// ---------------- hypernet: per-sample 9->100->147 (x2) ----------------
__global__ void hyper_kernel(const float* __restrict__ kA,
                             const float* __restrict__ w1a, const float* __restrict__ b1a,
                             const float* __restrict__ w2a, const float* __restrict__ b2a,
                             const float* __restrict__ w1b, const float* __restrict__ b1b,
                             const float* __restrict__ w2b, const float* __restrict__ b2b) {
    int b = blockIdx.x;
    __shared__ float a[9], h1[100], h2[100];
    int t = threadIdx.x;
    if (t < 9) a[t] = kA[b*9 + t];
    __syncthreads();
    if (t < 100) {
        float s = b1a[t];
        #pragma unroll
        for (int i = 0; i < 9; i++) s += a[i] * w1a[i*100 + t];
        h1[t] = gelu_exact(s);
    } else if (t < 200) {
        int h = t - 100;
        float s = b1b[h];
        #pragma unroll
        for (int i = 0; i < 9; i++) s += a[i] * w1b[i*100 + h];
        h2[h] = gelu_exact(s);
    }
    __syncthreads();
    for (int o = t; o < 147; o += blockDim.x) {
        float s1 = b2a[o], s2 = b2b[o];
        for (int h = 0; h < 100; h++) {
            s1 += h1[h] * w2a[h*147 + o];
            s2 += h2[h] * w2b[h*147 + o];
        }
        g_w1[b*147 + o] = s1;
        g_w2[b*147 + o] = s2;
    }
}

// ---------------- ConvTranspose chain ----------------
// ct1: in [B,1,3,3] -> out [B,32,5,5], stride 2 pad 1, gelu
__global__ void ct1_kernel(const float* __restrict__ kA,
                           const float* __restrict__ w, const float* __restrict__ bias) {
    int b = blockIdx.x;
    __shared__ float a[9];
    if (threadIdx.x < 9) a[threadIdx.x] = kA[b*9 + threadIdx.x];
    __syncthreads();
    for (int el = threadIdx.x; el < 32*25; el += blockDim.x) {
        int o = el / 25, rem = el % 25, y = rem / 5, x = rem % 5;
        float acc = bias[o];
        #pragma unroll
        for (int ky = 0; ky < 3; ky++) {
            int ty = y + 1 - ky;
            if (ty & 1) continue;
            int iy = ty >> 1;
            if (iy < 0 || iy >= 3) continue;
            #pragma unroll
            for (int kx = 0; kx < 3; kx++) {
                int tx = x + 1 - kx;
                if (tx & 1) continue;
                int ix = tx >> 1;
                if (ix < 0 || ix >= 3) continue;
                acc += a[iy*3 + ix] * w[o*9 + ky*3 + kx];  // w[0][o][ky][kx]
            }
        }
        g_a1[(b*32 + o)*25 + rem] = gelu_exact(acc);
    }
}

// mid ct: 32->32 channels, stride 2 pad 1, gelu. grid (B, 32)
__global__ void ct_mid_kernel(const float* __restrict__ in, const float* __restrict__ w,
                              const float* __restrict__ bias, float* __restrict__ out,
                              int inH, int outH) {
    int b = blockIdx.x, o = blockIdx.y;
    extern __shared__ float sm[];
    float* sin_ = sm;                    // 32*inH*inH
    float* sw   = sm + 32*inH*inH;       // 288
    int inSz = 32*inH*inH;
    const float* inb = in + b*inSz;
    for (int i = threadIdx.x; i < inSz; i += blockDim.x) sin_[i] = inb[i];
    for (int i = threadIdx.x; i < 32*9; i += blockDim.x)
        sw[i] = w[(i/9)*32*9 + o*9 + (i%9)];   // w[i][o][ky][kx]
    __syncthreads();
    float bo = bias[o];
    int outSz = outH*outH;
    for (int el = threadIdx.x; el < outSz; el += blockDim.x) {
        int y = el / outH, x = el % outH;
        float acc = bo;
        #pragma unroll
        for (int ky = 0; ky < 3; ky++) {
            int ty = y + 1 - ky;
            if (ty & 1) continue;
            int iy = ty >> 1;
            if (iy < 0 || iy >= inH) continue;
            #pragma unroll
            for (int kx = 0; kx < 3; kx++) {
                int tx = x + 1 - kx;
                if (tx & 1) continue;
                int ix = tx >> 1;
                if (ix < 0 || ix >= inH) continue;
                int base = iy*inH + ix;
                #pragma unroll 8
                for (int i = 0; i < 32; i++)
                    acc += sin_[i*inH*inH + base] * sw[i*9 + ky*3 + kx];
            }
        }
        out[(b*32 + o)*outSz + el] = gelu_exact(acc);
    }
}

// ct5: 32->2 channels, stride 2 pad 2, in 33 -> out 63, NO gelu. grid (B,2)
__global__ void ct5_kernel(const float* __restrict__ w, const float* __restrict__ bias) {
    int b = blockIdx.x, o = blockIdx.y;
    __shared__ float sw[32*9];
    for (int i = threadIdx.x; i < 32*9; i += blockDim.x)
        sw[i] = w[(i/9)*2*9 + o*9 + (i%9)];   // w[i][o][ky][kx], out layout [32][2][3][3]
    __syncthreads();
    float bo = bias[o];
    const float* inb = g_a4 + b*32*33*33;
    for (int el = threadIdx.x; el < NP; el += blockDim.x) {
        int y = el / NN, x = el % NN;
        float acc = bo;
        #pragma unroll
        for (int ky = 0; ky < 3; ky++) {
            int ty = y + 2 - ky;
            if (ty & 1) continue;
            int iy = ty >> 1;
            if (iy < 0 || iy >= 33) continue;
            #pragma unroll
            for (int kx = 0; kx < 3; kx++) {
                int tx = x + 2 - kx;
                if (tx & 1) continue;
                int ix = tx >> 1;
                if (ix < 0 || ix >= 33) continue;
                int base = iy*33 + ix;
                #pragma unroll 8
                for (int i = 0; i < 32; i++)
                    acc += __ldg(&inb[i*33*33 + base]) * sw[i*9 + ky*3 + kx];
            }
        }
        g_h[(b*2 + o)*NP + el] = acc;
    }
}

// ---------------- persistent per-sample solver ----------------
// smem layout (floats):
// sx 0, sf 3969, sr 7938, swcr 11907, swci 15876, sct 19845, sst 23814,
// sU 27783 (16080), ska 43863, sw1 43872, sw2 44019  => total 44166 floats
#define SMEM_FLOATS 44166

__device__ __forceinline__ void compute_residual(float* __restrict__ sr,
                                                 const float* __restrict__ sx,
                                                 const float* __restrict__ sf,
                                                 const float* __restrict__ ska,
                                                 int t, int T) {
    for (int el = t; el < NP; el += T) {
        int i = el / NN, j = el % NN;
        float acc = 0.f;
        #pragma unroll
        for (int di = 0; di < 3; di++) {
            int a = i + di;                 // padded row coord 0..64
            #pragma unroll
            for (int dj = 0; dj < 3; dj++) {
                int bb = j + dj;            // padded col coord 0..64
                float v;
                if (a == 64 || bb == 64) v = 1.0f;            // ones pad wins
                else if (a == 0 || bb == 0) v = 0.0f;         // zeros pad
                else v = sx[(a-1)*NN + (bb-1)];
                acc += ska[di*3 + dj] * v;
            }
        }
        sr[el] = sf[el] - acc;
    }
}

__global__ void solver_kernel(const float* __restrict__ x_in,
                              const float* __restrict__ f_in,
                              const float* __restrict__ kA) {
    extern __shared__ float sm[];
    float* sx   = sm;
    float* sf   = sm + NP;
    float* sr   = sm + 2*NP;
    float* swcr = sm + 3*NP;
    float* swci = sm + 4*NP;
    float* sct  = sm + 5*NP;
    float* sst  = sm + 6*NP;
    float* sU   = sm + 7*NP;          // 16080 floats scratch (t / S / C / D)
    float* ska  = sU + 16080;
    float* sw1  = ska + 9;
    float* sw2  = sw1 + 147;

    int b = blockIdx.x, t = threadIdx.x, T = blockDim.x;
    const float inv = 0.12598815766974242f;  // 1/sqrt(63)

    for (int el = t; el < NP; el += T) {
        sx[el]   = x_in[b*NP + el];
        sf[el]   = f_in[b*NP + el];
        swcr[el] = g_h[b*2*NP + 2*el];
        swci[el] = g_h[b*2*NP + 2*el + 1];
        sct[el]  = g_cosT[el];
        sst[el]  = g_sinT[el];
    }
    if (t < 9) ska[t] = kA[b*9 + t];
    for (int el = t; el < 147; el += T) {
        sw1[el] = g_w1[b*147 + el];
        sw2[el] = g_w2[b*147 + el];
    }
    __syncthreads();

    for (int iter = 0; iter < 5; iter++) {
        // ---- smoother: r = residual(x) ----
        compute_residual(sr, sx, sf, ska, t, T);
        __syncthreads();
        // t[c] = conv7(r, w1[c])   (zero padded 3)
        for (int el = t; el < 3*NP; el += T) {
            int c = el / NP, rem = el % NP, i = rem / NN, j = rem % NN;
            float acc = 0.f;
            #pragma unroll
            for (int u = 0; u < KS; u++) {
                int ii = i + u - 3;
                if (ii < 0 || ii >= NN) continue;
                #pragma unroll
                for (int v = 0; v < KS; v++) {
                    int jj = j + v - 3;
                    if (jj < 0 || jj >= NN) continue;
                    acc += sr[ii*NN + jj] * sw1[c*49 + u*7 + v];
                }
            }
            sU[el] = acc;
        }
        __syncthreads();
        // x += conv7(t, w2) summed over c
        for (int el = t; el < NP; el += T) {
            int i = el / NN, j = el % NN;
            float acc = 0.f;
            #pragma unroll
            for (int c = 0; c < ML; c++) {
                #pragma unroll
                for (int u = 0; u < KS; u++) {
                    int ii = i + u - 3;
                    if (ii < 0 || ii >= NN) continue;
                    #pragma unroll
                    for (int v = 0; v < KS; v++) {
                        int jj = j + v - 3;
                        if (jj < 0 || jj >= NN) continue;
                        acc += sU[c*NP + ii*NN + jj] * sw2[c*49 + u*7 + v];
                    }
                }
            }
            sx[el] += acc;
        }
        __syncthreads();

        // ---- coarse correction: r = residual(x) ----
        compute_residual(sr, sx, sf, ska, t, T);
        __syncthreads();

        // S[k1,n] = inv * sum_m W*[k1,m] r[m,n]   (forward, rows)
        float* Sr = sU;
        float* Si = sU + NP;
        for (int el = t; el < NP; el += T) {
            int k1 = el / NN, n = el % NN;
            float ar = 0.f, ai = 0.f;
            const float* cT = sct + k1*NN;
            const float* sT = sst + k1*NN;
            #pragma unroll 7
            for (int m = 0; m < NN; m++) {
                float rv = sr[m*NN + n];
                ar += cT[m] * rv;
                ai -= sT[m] * rv;
            }
            Sr[el] = ar * inv;
            Si[el] = ai * inv;
        }
        __syncthreads();
        // C[k1,k2] = (inv * sum_n S[k1,n] W*[k2,n]) * wc[k1,k2]   k2 < 32
        float* Cr = sU + 2*NP;
        float* Ci = Cr + 2016;
        for (int el = t; el < 63*HALFC; el += T) {
            int k1 = el >> 5, k2 = el & 31;
            float ar = 0.f, ai = 0.f;
            const float* cT = sct + k2*NN;
            const float* sT = sst + k2*NN;
            const float* srow = Sr + k1*NN;
            const float* sirow = Si + k1*NN;
            #pragma unroll 7
            for (int n = 0; n < NN; n++) {
                float c = cT[n], s = sT[n];
                float a = srow[n], bI = sirow[n];
                ar += a*c + bI*s;
                ai += bI*c - a*s;
            }
            ar *= inv; ai *= inv;
            float wr = swcr[k1*NN + k2], wi = swci[k1*NN + k2];
            Cr[el] = ar*wr - ai*wi;
            Ci[el] = ar*wi + ai*wr;
        }
        __syncthreads();
        // D[m,k2] = inv * sum_k1 W[m,k1] C[k1,k2]   (inverse over rows)
        float* Dr = sU + 2*NP + 4032;
        float* Di = Dr + 2016;
        for (int el = t; el < 63*HALFC; el += T) {
            int m = el >> 5, k2 = el & 31;
            float ar = 0.f, ai = 0.f;
            const float* cT = sct + m*NN;
            const float* sT = sst + m*NN;
            #pragma unroll 7
            for (int k1 = 0; k1 < NN; k1++) {
                float c = cT[k1], s = sT[k1];
                float cr = Cr[k1*HALFC + k2], ci = Ci[k1*HALFC + k2];
                ar += cr*c - ci*s;
                ai += cr*s + ci*c;
            }
            Dr[el] = ar * inv;
            Di[el] = ai * inv;
        }
        __syncthreads();
        // x[m,n] += inv * (Re D[m,0] + 2 sum_{k2=1..31} Re(D[m,k2] e^{i th}))
        for (int el = t; el < NP; el += T) {
            int m = el / NN, n = el % NN;
            float acc = Dr[m*HALFC];
            const float* drow = Dr + m*HALFC;
            const float* dirow = Di + m*HALFC;
            #pragma unroll 7
            for (int k2 = 1; k2 < HALFC; k2++) {
                float c = sct[k2*NN + n], s = sst[k2*NN + n];
                acc += 2.0f * (drow[k2]*c - dirow[k2]*s);
            }
            sx[el] += acc * inv;
        }
        __syncthreads();
    }

    // final residual + block sum of squares
    compute_residual(sr, sx, sf, ska, t, T);
    __syncthreads();
    float loc = 0.f;
    for (int el = t; el < NP; el += T) {
        float v = sr[el];
        loc += v * v;
    }
    #pragma unroll
    for (int off = 16; off; off >>= 1)
        loc += __shfl_xor_sync(0xFFFFFFFFu, loc, off);
    __shared__ float wsum[16];
    int wid = t >> 5;
    if ((t & 31) == 0) wsum[wid] = loc;
    __syncthreads();
    if (t == 0) {
        float s = 0.f;
        int nw = T >> 5;
        for (int w = 0; w < nw; w++) s += wsum[w];
        g_blocksum[b] = s;
    }
}

__global__ void final_reduce_kernel(float* __restrict__ out) {
    __shared__ float s[BATCH];
    s[threadIdx.x] = g_blocksum[threadIdx.x];
    __syncthreads();
    for (int st = BATCH/2; st > 0; st >>= 1) {
        if (threadIdx.x < st) s[threadIdx.x] += s[threadIdx.x + st];
        __syncthreads();
    }
    if (threadIdx.x == 0) out[0] = sqrtf(s[0]) / 256.0f;
}

// ---------------- host ----------------
extern "C" void kernel_launch(void* const* d_in, const int* in_sizes, int n_in,
                              void* d_out, int out_size) {
    const float* x      = (const float*)d_in[0];
    const float* f      = (const float*)d_in[1];
    const float* kA     = (const float*)d_in[2];
    const float* fc1_w1 = (const float*)d_in[3];
    const float* fc1_b1 = (const float*)d_in[4];
    const float* fc1_w2 = (const float*)d_in[5];
    const float* fc1_b2 = (const float*)d_in[6];
    const float* fc2_w1 = (const float*)d_in[7];
    const float* fc2_b1 = (const float*)d_in[8];
    const float* fc2_w2 = (const float*)d_in[9];
    const float* fc2_b2 = (const float*)d_in[10];
    const float* ct1_w  = (const float*)d_in[11];
    const float* ct1_b  = (const float*)d_in[12];
    const float* ct2_w  = (const float*)d_in[13];
    const float* ct2_b  = (const float*)d_in[14];
    const float* ct3_w  = (const float*)d_in[15];
    const float* ct3_b  = (const float*)d_in[16];
    const float* ct4_w  = (const float*)d_in[17];
    const float* ct4_b  = (const float*)d_in[18];
    const float* ct5_w  = (const float*)d_in[19];
    const float* ct5_b  = (const float*)d_in[20];
    float* out = (float*)d_out;

    static bool attr_set = false;
    // idempotent, no work: allowed to repeat every call
    cudaFuncSetAttribute(solver_kernel, cudaFuncAttributeMaxDynamicSharedMemorySize,
                         SMEM_FLOATS * (int)sizeof(float));
    (void)attr_set;

    init_tw_kernel<<<(NP + 255)/256, 256>>>();
    hyper_kernel<<<BATCH, 256>>>(kA, fc1_w1, fc1_b1, fc1_w2, fc1_b2,
                                 fc2_w1, fc2_b1, fc2_w2, fc2_b2);
    ct1_kernel<<<BATCH, 256>>>(kA, ct1_w, ct1_b);
    {
        int inH = 5, outH = 9;
        size_t sh = (32*inH*inH + 288) * sizeof(float);
        ct_mid_kernel<<<dim3(BATCH, 32), 256, sh>>>(g_a1, ct2_w, ct2_b, g_a2, inH, outH);
    }
    {
        int inH = 9, outH = 17;
        size_t sh = (32*inH*inH + 288) * sizeof(float);
        ct_mid_kernel<<<dim3(BATCH, 32), 256, sh>>>(g_a2, ct3_w, ct3_b, g_a3, inH, outH);
    }
    {
        int inH = 17, outH = 33;
        size_t sh = (32*inH*inH + 288) * sizeof(float);
        ct_mid_kernel<<<dim3(BATCH, 32), 256, sh>>>(g_a3, ct4_w, ct4_b, g_a4, inH, outH);
    }
    ct5_kernel<<<dim3(BATCH, 2), 256>>>(ct5_w, ct5_b);
    solver_kernel<<<BATCH, 512, SMEM_FLOATS * sizeof(float)>>>(x, f, kA);
    final_reduce_kernel<<<1, BATCH>>>(out);
}

// round 2
// speedup vs baseline: 2.2140x; 2.2140x over previous
#include <cuda_runtime.h>
#include <math.h>

#define NN 63
#define NP (NN*NN)          // 3969
#define NP64 4032           // 63*64 padded
#define BATCH 256
#define KS 7
#define ML 3
#define HALFC 32

// ---------------- device scratch ----------------
__device__ float g_cosT[NP];
__device__ float g_sinT[NP];
__device__ float g_w1[BATCH*147];
__device__ float g_w2[BATCH*147];
__device__ float g_a1[BATCH*25*32];     // [b][pix][ch]
__device__ float g_a2[BATCH*81*32];
__device__ float g_a3[BATCH*289*32];
__device__ float g_a4[BATCH*1089*32];
__device__ float g_h [BATCH*2*NP];      // channel-major [b][2][63*63] raw
__device__ float g_blocksum[BATCH];

__device__ __forceinline__ float gelu_exact(float v) {
    return v * 0.5f * (1.0f + erff(v * 0.70710678118654752f));
}

// ---------------- twiddle init ----------------
__global__ void init_tw_kernel() {
    int idx = blockIdx.x * blockDim.x + threadIdx.x;
    if (idx < NP) {
        int k = idx / NN, n = idx % NN;
        float ang = 6.28318530717958647692f * (float)((k * n) % NN) / 63.0f;
        g_cosT[idx] = cosf(ang);
        g_sinT[idx] = sinf(ang);
    }
}

// ---------------- hypernet: per-sample 9->100->147 (x2) ----------------
__global__ void hyper_kernel(const float* __restrict__ kA,
                             const float* __restrict__ w1a, const float* __restrict__ b1a,
                             const float* __restrict__ w2a, const float* __restrict__ b2a,
                             const float* __restrict__ w1b, const float* __restrict__ b1b,
                             const float* __restrict__ w2b, const float* __restrict__ b2b) {
    int b = blockIdx.x;
    __shared__ float a[9], h1[100], h2[100];
    int t = threadIdx.x;
    if (t < 9) a[t] = kA[b*9 + t];
    __syncthreads();
    if (t < 100) {
        float s = b1a[t];
        #pragma unroll
        for (int i = 0; i < 9; i++) s += a[i] * w1a[i*100 + t];
        h1[t] = gelu_exact(s);
    } else if (t < 200) {
        int h = t - 100;
        float s = b1b[h];
        #pragma unroll
        for (int i = 0; i < 9; i++) s += a[i] * w1b[i*100 + h];
        h2[h] = gelu_exact(s);
    }
    __syncthreads();
    for (int o = t; o < 147; o += blockDim.x) {
        float s1 = b2a[o], s2 = b2b[o];
        for (int h = 0; h < 100; h++) {
            s1 += h1[h] * w2a[h*147 + o];
            s2 += h2[h] * w2b[h*147 + o];
        }
        g_w1[b*147 + o] = s1;
        g_w2[b*147 + o] = s2;
    }
}

// ---------------- ConvTranspose chain (pixel-major layouts) ----------------
// ct1: [B,1,3,3] -> [B][25][32], stride 2 pad 1, gelu
__global__ void ct1_kernel(const float* __restrict__ kA,
                           const float* __restrict__ w, const float* __restrict__ bias) {
    int b = blockIdx.x;
    __shared__ float a[9];
    if (threadIdx.x < 9) a[threadIdx.x] = kA[b*9 + threadIdx.x];
    __syncthreads();
    for (int el = threadIdx.x; el < 32*25; el += blockDim.x) {
        int pix = el >> 5, o = el & 31;
        int y = pix / 5, x = pix % 5;
        float acc = bias[o];
        int kys[2], iys[2], nky, kxs[2], ixs[2], nkx;
        if (y & 1) { nky = 2; kys[0]=0; iys[0]=(y+1)>>1; kys[1]=2; iys[1]=(y-1)>>1; }
        else       { nky = 1; kys[0]=1; iys[0]=y>>1; }
        if (x & 1) { nkx = 2; kxs[0]=0; ixs[0]=(x+1)>>1; kxs[1]=2; ixs[1]=(x-1)>>1; }
        else       { nkx = 1; kxs[0]=1; ixs[0]=x>>1; }
        for (int p = 0; p < nky; p++)
            for (int q = 0; q < nkx; q++)
                acc += a[iys[p]*3 + ixs[q]] * w[o*9 + kys[p]*3 + kxs[q]];
        g_a1[(b*25 + pix)*32 + o] = gelu_exact(acc);
    }
}

// mid ct: 32->32, stride 2 pad 1, gelu. grid (B, 4): 8 out-ch per block.
template <int IN_H>
__global__ void __launch_bounds__(256) ct_mid_kernel(const float* __restrict__ in,
                              const float* __restrict__ w,
                              const float* __restrict__ bias, float* __restrict__ out) {
    constexpr int OUT_H = 2*IN_H - 1;
    constexpr int IN_SZ = IN_H*IN_H;
    constexpr int OUT_SZ = OUT_H*OUT_H;
    __shared__ float s_in[IN_SZ*32];
    __shared__ float s_w[9*8*32];
    __shared__ float s_b[8];
    int b = blockIdx.x, og = blockIdx.y, tid = threadIdx.x;
    int o_base = og * 8;
    const float4* gin = (const float4*)(in + (size_t)b * IN_SZ * 32);
    float4* s_in4w = (float4*)s_in;
    for (int idx = tid; idx < IN_SZ*8; idx += 256) s_in4w[idx] = gin[idx];
    for (int idx = tid; idx < 2304; idx += 256) {
        int k = idx >> 8, r = idx & 255, ol = r >> 5, i = r & 31;
        s_w[idx] = w[(i*32 + o_base + ol)*9 + k];
    }
    if (tid < 8) s_b[tid] = bias[o_base + tid];
    __syncthreads();

    const float4* s_in4 = (const float4*)s_in;
    const float4* s_w4  = (const float4*)s_w;
    for (int pix = tid; pix < OUT_SZ; pix += 256) {
        int y = pix / OUT_H, x = pix % OUT_H;
        float acc[8];
        #pragma unroll
        for (int ol = 0; ol < 8; ol++) acc[ol] = s_b[ol];
        int kys[2], iys[2], nky, kxs[2], ixs[2], nkx;
        if (y & 1) { nky = 2; kys[0]=0; iys[0]=(y+1)>>1; kys[1]=2; iys[1]=(y-1)>>1; }
        else       { nky = 1; kys[0]=1; iys[0]=y>>1; }
        if (x & 1) { nkx = 2; kxs[0]=0; ixs[0]=(x+1)>>1; kxs[1]=2; ixs[1]=(x-1)>>1; }
        else       { nkx = 1; kxs[0]=1; ixs[0]=x>>1; }
        for (int p = 0; p < nky; p++)
            for (int q = 0; q < nkx; q++) {
                int base4 = (iys[p]*IN_H + ixs[q]) * 8;
                int kk = kys[p]*3 + kxs[q];
                #pragma unroll
                for (int c4 = 0; c4 < 8; c4++) {
                    float4 v = s_in4[base4 + c4];
                    #pragma unroll
                    for (int ol = 0; ol < 8; ol++) {
                        float4 wv = s_w4[kk*64 + ol*8 + c4];
                        acc[ol] += v.x*wv.x + v.y*wv.y + v.z*wv.z + v.w*wv.w;
                    }
                }
            }
        float* ob = out + ((size_t)(b*OUT_SZ + pix))*32 + o_base;
        float4 o0 = {gelu_exact(acc[0]), gelu_exact(acc[1]), gelu_exact(acc[2]), gelu_exact(acc[3])};
        float4 o1 = {gelu_exact(acc[4]), gelu_exact(acc[5]), gelu_exact(acc[6]), gelu_exact(acc[7])};
        *(float4*)(ob)     = o0;
        *(float4*)(ob + 4) = o1;
    }
}

// ct5: 32->2, stride 2 pad 2, in 33 -> out 63, NO gelu. grid B.
__global__ void __launch_bounds__(256) ct5_kernel(const float* __restrict__ w, const float* __restrict__ bias) {
    __shared__ float s_w[9*2*32];
    int b = blockIdx.x, tid = threadIdx.x;
    for (int idx = tid; idx < 576; idx += 256) {
        int k = idx / 64, r = idx & 63, o = r >> 5, i = r & 31;
        s_w[idx] = w[i*18 + o*9 + k];      // layout [32][2][3][3]
    }
    __syncthreads();
    float b0 = bias[0], b1 = bias[1];
    const float4* s_w4 = (const float4*)s_w;
    const float4* gin = (const float4*)(g_a4 + (size_t)b * 1089 * 32);
    for (int pix = tid; pix < NP; pix += 256) {
        int y = pix / NN, x = pix % NN;
        float acc0 = b0, acc1 = b1;
        int kys[2], iys[2], nky, kxs[2], ixs[2], nkx;
        if (y & 1) { nky = 1; kys[0]=1; iys[0]=(y+1)>>1; }
        else       { nky = 2; kys[0]=0; iys[0]=(y+2)>>1; kys[1]=2; iys[1]=y>>1; }
        if (x & 1) { nkx = 1; kxs[0]=1; ixs[0]=(x+1)>>1; }
        else       { nkx = 2; kxs[0]=0; ixs[0]=(x+2)>>1; kxs[1]=2; ixs[1]=x>>1; }
        for (int p = 0; p < nky; p++)
            for (int q = 0; q < nkx; q++) {
                int base4 = (iys[p]*33 + ixs[q]) * 8;
                int kk = kys[p]*3 + kxs[q];
                #pragma unroll
                for (int c4 = 0; c4 < 8; c4++) {
                    float4 v = __ldg(gin + base4 + c4);
                    float4 w0 = s_w4[kk*16 + c4];
                    float4 w1 = s_w4[kk*16 + 8 + c4];
                    acc0 += v.x*w0.x + v.y*w0.y + v.z*w0.z + v.w*w0.w;
                    acc1 += v.x*w1.x + v.y*w1.y + v.z*w1.z + v.w*w1.w;
                }
            }
        g_h[((size_t)b*2 + 0)*NP + pix] = acc0;
        g_h[((size_t)b*2 + 1)*NP + pix] = acc1;
    }
}

// ---------------- persistent per-sample solver ----------------
// smem (floats): sxp 4420 | srp 4968 | stp 14904 | swcr 2016 | swci 2016 |
//                sct 4032 | sst 4032 | sf 4032 | ska 16 | sw1 160 | sw2 160
#define OFF_SXP 0
#define OFF_SRP 4420
#define OFF_STP (OFF_SRP + 4968)
#define OFF_WCR (OFF_STP + 14904)
#define OFF_WCI (OFF_WCR + 2016)
#define OFF_CT  (OFF_WCI + 2016)
#define OFF_ST  (OFF_CT + 4032)
#define OFF_F   (OFF_ST + 4032)
#define OFF_KA  (OFF_F + 4032)
#define OFF_W1  (OFF_KA + 16)
#define OFF_W2  (OFF_W1 + 160)
#define SMEM_FLOATS (OFF_W2 + 160)

__global__ void __launch_bounds__(512) solver_kernel(const float* __restrict__ x_in,
                              const float* __restrict__ f_in,
                              const float* __restrict__ kA) {
    extern __shared__ float sm[];
    float* sxp  = sm + OFF_SXP;   // 65 x 68 padded x (BCs baked)
    float* srp  = sm + OFF_SRP;   // 69 x 72 zero-padded residual
    float* stp  = sm + OFF_STP;   // 3 x (69 x 72) conv mid / DFT scratch overlay
    float* swcr = sm + OFF_WCR;   // 63 x 32
    float* swci = sm + OFF_WCI;
    float* sct  = sm + OFF_CT;    // 63 x 64
    float* sst  = sm + OFF_ST;
    float* sf   = sm + OFF_F;     // 63 x 64
    float* ska  = sm + OFF_KA;
    float* sw1  = sm + OFF_W1;
    float* sw2  = sm + OFF_W2;

    int b = blockIdx.x, t = threadIdx.x;
    const int T = 512;
    const float inv = 0.12598815766974242f;  // 1/sqrt(63)

    // ---- init ----
    for (int el = t; el < NP64; el += T) {
        int i = el >> 6, j = el & 63;
        if (j < 63) {
            sxp[(i+1)*68 + (j+1)] = x_in[b*NP + i*NN + j];
            sf[el] = f_in[b*NP + i*NN + j];
            sct[el] = g_cosT[i*NN + j];
            sst[el] = g_sinT[i*NN + j];
        } else {
            sf[el] = 0.f; sct[el] = 0.f; sst[el] = 0.f;
        }
    }
    for (int c = t; c < 65; c += T) {
        sxp[c] = (c == 64) ? 1.f : 0.f;          // top row
        sxp[64*68 + c] = 1.f;                    // bottom row
    }
    for (int r = t; r < 65; r += T) {
        sxp[r*68] = (r == 64) ? 1.f : 0.f;       // left col
        sxp[r*68 + 64] = 1.f;                    // right col
    }
    for (int el = t; el < 4968; el += T) srp[el] = 0.f;
    for (int el = t; el < 2016; el += T) {
        int k1 = el >> 5, k2 = el & 31;
        int pix = k1*NN + k2;
        swcr[el] = g_h[(size_t)b*2*NP + 2*pix];
        swci[el] = g_h[(size_t)b*2*NP + 2*pix + 1];
    }
    if (t < 9) ska[t] = kA[b*9 + t];
    for (int el = t; el < 147; el += T) {
        sw1[el] = g_w1[b*147 + el];
        sw2[el] = g_w2[b*147 + el];
    }
    __syncthreads();

    float* Sr = stp;               // 63x64
    float* Si = stp + 4032;
    float* Cr = stp + 8064;        // 63x32
    float* Ci = stp + 10080;
    float* Dr = stp;               // 63x32 (S dead)
    float* Di = stp + 2016;

    for (int iter = 0; iter < 5; iter++) {
        // ---- (a) residual -> srp ; zero stp ----
        for (int el = t; el < NP64; el += T) {
            int i = el >> 6, j = el & 63;
            if (j >= 63) continue;
            const float* xb = sxp + i*68 + j;
            float acc = ska[0]*xb[0] + ska[1]*xb[1] + ska[2]*xb[2]
                      + ska[3]*xb[68] + ska[4]*xb[69] + ska[5]*xb[70]
                      + ska[6]*xb[136] + ska[7]*xb[137] + ska[8]*xb[138];
            srp[(i+3)*72 + j + 4] = sf[el] - acc;
        }
        for (int el = t; el < 14904; el += T) stp[el] = 0.f;
        __syncthreads();

        // ---- (b) stage1: stp[c] = conv7(srp, w1[c]) ----
        for (int w = t; w < 3072; w += T) {
            int c = w >> 10, r = w & 1023, i = r >> 4, g = r & 15;
            if (i >= 63) continue;
            int j0 = g << 2;
            float a0=0.f, a1=0.f, a2=0.f, a3=0.f;
            const float* wc_ = sw1 + c*49;
            #pragma unroll
            for (int u = 0; u < 7; u++) {
                const float4* rp = (const float4*)(srp + (i+u)*72 + j0);
                float4 A = rp[0], B = rp[1], C = rp[2];
                float rr[12] = {A.x,A.y,A.z,A.w, B.x,B.y,B.z,B.w, C.x,C.y,C.z,C.w};
                #pragma unroll
                for (int v = 0; v < 7; v++) {
                    float wv = wc_[u*7 + v];
                    a0 += rr[v+1]*wv; a1 += rr[v+2]*wv;
                    a2 += rr[v+3]*wv; a3 += rr[v+4]*wv;
                }
            }
            float* o = stp + c*4968 + (i+3)*72 + j0 + 4;
            if (g < 15) { float4 ov = {a0,a1,a2,a3}; *(float4*)o = ov; }
            else { o[0]=a0; o[1]=a1; o[2]=a2; }
        }
        __syncthreads();

        // ---- (c) stage2: sxp += conv7(stp, w2) summed over c ----
        for (int w = t; w < 1024; w += T) {
            int i = w >> 4, g = w & 15;
            if (i >= 63) continue;
            int j0 = g << 2;
            float a0=0.f, a1=0.f, a2=0.f, a3=0.f;
            #pragma unroll
            for (int c = 0; c < 3; c++) {
                const float* tb = stp + c*4968;
                const float* wc_ = sw2 + c*49;
                #pragma unroll
                for (int u = 0; u < 7; u++) {
                    const float4* rp = (const float4*)(tb + (i+u)*72 + j0);
                    float4 A = rp[0], B = rp[1], C = rp[2];
                    float rr[12] = {A.x,A.y,A.z,A.w, B.x,B.y,B.z,B.w, C.x,C.y,C.z,C.w};
                    #pragma unroll
                    for (int v = 0; v < 7; v++) {
                        float wv = wc_[u*7 + v];
                        a0 += rr[v+1]*wv; a1 += rr[v+2]*wv;
                        a2 += rr[v+3]*wv; a3 += rr[v+4]*wv;
                    }
                }
            }
            float* xo = sxp + (i+1)*68 + j0 + 1;
            xo[0] += a0; xo[1] += a1; xo[2] += a2;
            if (g < 15) xo[3] += a3;
        }
        __syncthreads();

        // ---- (d) residual -> srp ----
        for (int el = t; el < NP64; el += T) {
            int i = el >> 6, j = el & 63;
            if (j >= 63) continue;
            const float* xb = sxp + i*68 + j;
            float acc = ska[0]*xb[0] + ska[1]*xb[1] + ska[2]*xb[2]
                      + ska[3]*xb[68] + ska[4]*xb[69] + ska[5]*xb[70]
                      + ska[6]*xb[136] + ska[7]*xb[137] + ska[8]*xb[138];
            srp[(i+3)*72 + j + 4] = sf[el] - acc;
        }
        __syncthreads();

        // ---- (e) S[k1,n] = inv * sum_m W*[k1,m] r[m,n] ----
        for (int w = t; w < 1024; w += T) {
            int k1 = w >> 4, g = w & 15;
            if (k1 >= 63) continue;
            const float* cT = sct + k1*64;
            const float* sT = sst + k1*64;
            float arx=0,ary=0,arz=0,arw=0, aix=0,aiy=0,aiz=0,aiw=0;
            #pragma unroll 9
            for (int m = 0; m < 63; m++) {
                float c = cT[m], s = sT[m];
                float4 rv = *(const float4*)(srp + (m+3)*72 + 4 + (g<<2));
                arx += c*rv.x; ary += c*rv.y; arz += c*rv.z; arw += c*rv.w;
                aix -= s*rv.x; aiy -= s*rv.y; aiz -= s*rv.z; aiw -= s*rv.w;
            }
            float4 R = {arx*inv, ary*inv, arz*inv, arw*inv};
            float4 I = {aix*inv, aiy*inv, aiz*inv, aiw*inv};
            *(float4*)(Sr + k1*64 + (g<<2)) = R;
            *(float4*)(Si + k1*64 + (g<<2)) = I;
        }
        __syncthreads();

        // ---- (f) C[k1,k2] = (inv * sum_n S[k1,n] W*[k2,n]) * wc  (k2<32) ----
        for (int w = t; w < 512; w += T) {
            if (w >= 504) continue;
            int k1 = w >> 3, kg = w & 7, k20 = kg << 2;
            const float* sr_ = Sr + k1*64;
            const float* si_ = Si + k1*64;
            float arx=0,ary=0,arz=0,arw=0, aix=0,aiy=0,aiz=0,aiw=0;
            #pragma unroll 9
            for (int n = 0; n < 63; n++) {
                float a = sr_[n], bi = si_[n];
                float4 c4 = *(const float4*)(sct + n*64 + k20);  // symmetry
                float4 s4 = *(const float4*)(sst + n*64 + k20);
                arx += a*c4.x + bi*s4.x;  aix += bi*c4.x - a*s4.x;
                ary += a*c4.y + bi*s4.y;  aiy += bi*c4.y - a*s4.y;
                arz += a*c4.z + bi*s4.z;  aiz += bi*c4.z - a*s4.z;
                arw += a*c4.w + bi*s4.w;  aiw += bi*c4.w - a*s4.w;
            }
            float4 wr = *(const float4*)(swcr + k1*32 + k20);
            float4 wi = *(const float4*)(swci + k1*32 + k20);
            arx*=inv; ary*=inv; arz*=inv; arw*=inv;
            aix*=inv; aiy*=inv; aiz*=inv; aiw*=inv;
            float4 cr = {arx*wr.x - aix*wi.x, ary*wr.y - aiy*wi.y,
                         arz*wr.z - aiz*wi.z, arw*wr.w - aiw*wi.w};
            float4 ci = {arx*wi.x + aix*wr.x, ary*wi.y + aiy*wr.y,
                         arz*wi.z + aiz*wr.z, arw*wi.w + aiw*wr.w};
            *(float4*)(Cr + k1*32 + k20) = cr;
            *(float4*)(Ci + k1*32 + k20) = ci;
        }
        __syncthreads();

        // ---- (g) D[m,k2] = inv * sum_k1 W[m,k1] C[k1,k2] ----
        for (int w = t; w < 512; w += T) {
            if (w >= 504) continue;
            int m = w >> 3, kg = w & 7, k20 = kg << 2;
            const float* cT = sct + m*64;
            const float* sT = sst + m*64;
            float arx=0,ary=0,arz=0,arw=0, aix=0,aiy=0,aiz=0,aiw=0;
            #pragma unroll 9
            for (int k1 = 0; k1 < 63; k1++) {
                float c = cT[k1], s = sT[k1];
                float4 cr = *(const float4*)(Cr + k1*32 + k20);
                float4 ci = *(const float4*)(Ci + k1*32 + k20);
                arx += cr.x*c - ci.x*s;  aix += cr.x*s + ci.x*c;
                ary += cr.y*c - ci.y*s;  aiy += cr.y*s + ci.y*c;
                arz += cr.z*c - ci.z*s;  aiz += cr.z*s + ci.z*c;
                arw += cr.w*c - ci.w*s;  aiw += cr.w*s + ci.w*c;
            }
            float4 R = {arx*inv, ary*inv, arz*inv, arw*inv};
            float4 I = {aix*inv, aiy*inv, aiz*inv, aiw*inv};
            *(float4*)(Dr + m*32 + k20) = R;
            *(float4*)(Di + m*32 + k20) = I;
        }
        __syncthreads();

        // ---- (h) x[m,n] += inv*(Dr[m,0] + 2*sum_{k2=1..31} Re(D e^{i th})) ----
        for (int w = t; w < 1024; w += T) {
            int m = w >> 4, g = w & 15;
            if (m >= 63) continue;
            int n0 = g << 2;
            const float* dr_ = Dr + m*32;
            const float* di_ = Di + m*32;
            float d0 = dr_[0];
            float ax=d0, ay=d0, az=d0, aw=d0;
            #pragma unroll 31
            for (int k2 = 1; k2 < 32; k2++) {
                float dr = dr_[k2]*2.f, di = di_[k2]*2.f;
                float4 c4 = *(const float4*)(sct + k2*64 + n0);
                float4 s4 = *(const float4*)(sst + k2*64 + n0);
                ax += dr*c4.x - di*s4.x;
                ay += dr*c4.y - di*s4.y;
                az += dr*c4.z - di*s4.z;
                aw += dr*c4.w - di*s4.w;
            }
            float* xo = sxp + (m+1)*68 + n0 + 1;
            xo[0] += ax*inv; xo[1] += ay*inv; xo[2] += az*inv;
            if (g < 15) xo[3] += aw*inv;
        }
        __syncthreads();
    }

    // ---- final residual + sum of squares ----
    float loc = 0.f;
    for (int el = t; el < NP64; el += T) {
        int i = el >> 6, j = el & 63;
        if (j >= 63) continue;
        const float* xb = sxp + i*68 + j;
        float acc = ska[0]*xb[0] + ska[1]*xb[1] + ska[2]*xb[2]
                  + ska[3]*xb[68] + ska[4]*xb[69] + ska[5]*xb[70]
                  + ska[6]*xb[136] + ska[7]*xb[137] + ska[8]*xb[138];
        float v = sf[el] - acc;
        loc += v * v;
    }
    #pragma unroll
    for (int off = 16; off; off >>= 1)
        loc += __shfl_xor_sync(0xFFFFFFFFu, loc, off);
    __shared__ float wsum[16];
    int wid = t >> 5;
    if ((t & 31) == 0) wsum[wid] = loc;
    __syncthreads();
    if (t == 0) {
        float s = 0.f;
        #pragma unroll
        for (int w = 0; w < 16; w++) s += wsum[w];
        g_blocksum[b] = s;
    }
}

__global__ void final_reduce_kernel(float* __restrict__ out) {
    __shared__ float s[BATCH];
    s[threadIdx.x] = g_blocksum[threadIdx.x];
    __syncthreads();
    for (int st = BATCH/2; st > 0; st >>= 1) {
        if (threadIdx.x < st) s[threadIdx.x] += s[threadIdx.x + st];
        __syncthreads();
    }
    if (threadIdx.x == 0) out[0] = sqrtf(s[0]) / 256.0f;
}

// ---------------- host ----------------
extern "C" void kernel_launch(void* const* d_in, const int* in_sizes, int n_in,
                              void* d_out, int out_size) {
    const float* x      = (const float*)d_in[0];
    const float* f      = (const float*)d_in[1];
    const float* kA     = (const float*)d_in[2];
    const float* fc1_w1 = (const float*)d_in[3];
    const float* fc1_b1 = (const float*)d_in[4];
    const float* fc1_w2 = (const float*)d_in[5];
    const float* fc1_b2 = (const float*)d_in[6];
    const float* fc2_w1 = (const float*)d_in[7];
    const float* fc2_b1 = (const float*)d_in[8];
    const float* fc2_w2 = (const float*)d_in[9];
    const float* fc2_b2 = (const float*)d_in[10];
    const float* ct1_w  = (const float*)d_in[11];
    const float* ct1_b  = (const float*)d_in[12];
    const float* ct2_w  = (const float*)d_in[13];
    const float* ct2_b  = (const float*)d_in[14];
    const float* ct3_w  = (const float*)d_in[15];
    const float* ct3_b  = (const float*)d_in[16];
    const float* ct4_w  = (const float*)d_in[17];
    const float* ct4_b  = (const float*)d_in[18];
    const float* ct5_w  = (const float*)d_in[19];
    const float* ct5_b  = (const float*)d_in[20];
    float* out = (float*)d_out;

    cudaFuncSetAttribute(solver_kernel, cudaFuncAttributeMaxDynamicSharedMemorySize,
                         SMEM_FLOATS * (int)sizeof(float));

    init_tw_kernel<<<(NP + 255)/256, 256>>>();
    hyper_kernel<<<BATCH, 256>>>(kA, fc1_w1, fc1_b1, fc1_w2, fc1_b2,
                                 fc2_w1, fc2_b1, fc2_w2, fc2_b2);
    ct1_kernel<<<BATCH, 256>>>(kA, ct1_w, ct1_b);
    ct_mid_kernel<5> <<<dim3(BATCH, 4), 256>>>(g_a1, ct2_w, ct2_b, g_a2);
    ct_mid_kernel<9> <<<dim3(BATCH, 4), 256>>>(g_a2, ct3_w, ct3_b, g_a3);
    ct_mid_kernel<17><<<dim3(BATCH, 4), 256>>>(g_a3, ct4_w, ct4_b, g_a4);
    ct5_kernel<<<BATCH, 256>>>(ct5_w, ct5_b);
    solver_kernel<<<BATCH, 512, SMEM_FLOATS * sizeof(float)>>>(x, f, kA);
    final_reduce_kernel<<<1, BATCH>>>(out);
}